// round 1
// baseline (speedup 1.0000x reference)
#include <cuda_runtime.h>
#include <cstdint>

// Problem constants
//   x:            (512, 1024) f32
//   input_cores:  (10, 10, 2, 2, 10) f32   [i][r_in][p][c][r_out]
//   output_cores: (10, 10, 2, 2, 10) f32   [j][r_in][p][d][r_out]
//   central:      (1024, 1024) f32
//   bias:         (1, 1024) f32
//   out:          (512, 1024) f32
#define MROWS 51200   // 512 * 10 (l0) * 10 (r)

// Scratch (device globals: allocation-free kernel_launch)
__device__ float g_S[(size_t)MROWS * 1024];  // S^T: row=(b*10+l)*10+r, col=c   (also reused as partials)
__device__ float g_U[(size_t)MROWS * 1024];  // U:   row=(b*10+l)*10+r, col=d

// ---------------- f32x2 helpers (Blackwell packed fp32) ----------------
__device__ __forceinline__ uint64_t f2dup(float x) {
    uint64_t r; asm("mov.b64 %0, {%1, %1};" : "=l"(r) : "f"(x)); return r;
}
__device__ __forceinline__ uint64_t packf2(float lo, float hi) {
    uint64_t r; asm("mov.b64 %0, {%1, %2};" : "=l"(r) : "f"(lo), "f"(hi)); return r;
}
__device__ __forceinline__ uint64_t fma2(uint64_t a, uint64_t b, uint64_t c) {
    uint64_t d; asm("fma.rn.f32x2 %0, %1, %2, %3;" : "=l"(d) : "l"(a), "l"(b), "l"(c)); return d;
}
__device__ __forceinline__ float2 u2f2(uint64_t u) {
    float2 f; asm("mov.b64 {%0, %1}, %2;" : "=f"(f.x), "=f"(f.y) : "l"(u)); return f;
}

// ---------------- shared sweep step ----------------
// State layout in smem: flat[(C_idx*10 + bond)*Q + q], total 10240 floats.
// Step: out[((c*2+d)*10+s)*Qout + q] = sum_{a=(r,pbit)} in[(c*10+r)*Qin + pbit*Qout + q] * M[a*20 + (d*10+s)]
// M is a 20x20 row-major matrix in smem. 512 (c,q) output pairs; each thread does 2.
__device__ __forceinline__ void sweep_step(const float* __restrict__ cur,
                                           float* __restrict__ nxt,
                                           const float* __restrict__ M,
                                           int Qout, int lq, int tid)
{
    const int Qin = Qout << 1;
    const int j0 = tid, j1 = tid + 256;
    const int q0 = j0 & (Qout - 1), c0 = j0 >> lq;
    const int q1 = j1 & (Qout - 1), c1 = j1 >> lq;

    float v0[20], v1[20];
#pragma unroll
    for (int rr = 0; rr < 10; rr++) {
        int base0 = (c0 * 10 + rr) * Qin + q0;
        v0[2 * rr]     = cur[base0];
        v0[2 * rr + 1] = cur[base0 + Qout];
        int base1 = (c1 * 10 + rr) * Qin + q1;
        v1[2 * rr]     = cur[base1];
        v1[2 * rr + 1] = cur[base1 + Qout];
    }

    uint64_t acc0[10], acc1[10];
#pragma unroll
    for (int t = 0; t < 10; t++) { acc0[t] = 0ull; acc1[t] = 0ull; }

#pragma unroll
    for (int a = 0; a < 20; a++) {
        uint64_t va0 = f2dup(v0[a]);
        uint64_t va1 = f2dup(v1[a]);
        const uint64_t* M2 = (const uint64_t*)(M + a * 20);  // 8B-aligned (a*80 bytes)
#pragma unroll
        for (int b2 = 0; b2 < 10; b2++) {
            uint64_t m2 = M2[b2];           // LDS.64, warp-uniform broadcast
            acc0[b2] = fma2(va0, m2, acc0[b2]);
            acc1[b2] = fma2(va1, m2, acc1[b2]);
        }
    }

#pragma unroll
    for (int b2 = 0; b2 < 10; b2++) {
        float2 f0 = u2f2(acc0[b2]);
        float2 f1 = u2f2(acc1[b2]);
        const int bbA = 2 * b2, bbB = 2 * b2 + 1;     // bb = d*10+s
        const int dA = bbA / 10, sA = bbA % 10;
        const int dB = bbB / 10, sB = bbB % 10;
        nxt[((c0 * 2 + dA) * 10 + sA) * Qout + q0] = f0.x;
        nxt[((c0 * 2 + dB) * 10 + sB) * Qout + q0] = f0.y;
        nxt[((c1 * 2 + dA) * 10 + sA) * Qout + q1] = f1.x;
        nxt[((c1 * 2 + dB) * 10 + sB) * Qout + q1] = f1.y;
    }
}

// ---------------- Kernel 1: input sweep ----------------
// One CTA per (b, l0). Absorbs x into the 10 input cores, writes S^T to g_S.
__global__ __launch_bounds__(256) void input_sweep_kernel(const float* __restrict__ x,
                                                          const float* __restrict__ ic)
{
    extern __shared__ float sm[];
    float* xs   = sm;                 // 1024
    float* Mc   = sm + 1024;          // 4000 (raw cores; 'rpds' is already M[(r,p),(d,s)])
    float* bufA = sm + 1024 + 4000;   // 10240
    float* bufB = bufA + 10240;       // 10240
    const int tid = threadIdx.x;
    const int bl = blockIdx.x;
    const int b = bl / 10, l = bl % 10;

    for (int t = tid; t < 1024; t += 256) xs[t] = x[b * 1024 + t];
    for (int t = tid; t < 4000; t += 256) Mc[t] = ic[t];
    __syncthreads();

    // step 0: S0[(c*10+s)*512 + q] = sum_p x[b, p*512+q] * core0[l,p,c,s]
    for (int idx = tid; idx < 10240; idx += 256) {
        int q  = idx & 511;
        int cs = idx >> 9;            // c*10+s, in [0,20)
        int c = cs / 10, s = cs % 10;
        float w0 = Mc[((l * 2 + 0) * 2 + c) * 10 + s];
        float w1 = Mc[((l * 2 + 1) * 2 + c) * 10 + s];
        bufA[idx] = xs[q] * w0 + xs[512 + q] * w1;
    }

    float* cur = bufA;
    float* nxt = bufB;
    for (int i = 1; i < 10; i++) {
        __syncthreads();
        sweep_step(cur, nxt, Mc + i * 400, 512 >> i, 9 - i, tid);
        float* t = cur; cur = nxt; nxt = t;
    }
    __syncthreads();

    // final state: cur[c*10 + r], c in [0,1024), r in [0,10). Write transposed rows (coalesced).
    const size_t rowbase = (size_t)bl * 10;
    for (int idx = tid; idx < 10240; idx += 256) {
        int rr = idx >> 10, c = idx & 1023;
        g_S[rowbase * 1024 + idx] = cur[c * 10 + rr];   // row (rowbase+rr), col c
    }
}

// ---------------- Kernel 2: central GEMM (f32x2 SGEMM) ----------------
// U = g_S(51200x1024) @ central(1024x1024), all row-major fp32.
__global__ __launch_bounds__(256) void gemm_kernel(const float* __restrict__ Bm)
{
    __shared__ float As[16][132];   // [k][m], +4 pad
    __shared__ float Bs[16][128];   // [k][n]
    const int tid = threadIdx.x;
    const int m0 = blockIdx.y * 128;
    const int n0 = blockIdx.x * 128;
    const int tm = (tid >> 4) << 3;         // thread row offset (0..120)
    const int tn = (tid & 15) << 3;         // thread col offset (0..120)
    const int arow = tid >> 2;              // 0..63
    const int acol = (tid & 3) << 2;        // 0,4,8,12
    const int brow = tid >> 5;              // 0..7
    const int bcol = (tid & 31) << 2;       // 0..124

    const float* Ag = g_S + (size_t)(m0 + arow) * 1024 + acol;
    const float* Bg = Bm + (size_t)brow * 1024 + n0 + bcol;

    uint64_t acc[8][4];
#pragma unroll
    for (int i = 0; i < 8; i++)
#pragma unroll
        for (int j = 0; j < 4; j++) acc[i][j] = 0ull;

    for (int k0 = 0; k0 < 1024; k0 += 16) {
        float4 a0 = *(const float4*)(Ag + k0);
        float4 a1 = *(const float4*)(Ag + k0 + (size_t)64 * 1024);
        float4 b0 = *(const float4*)(Bg + (size_t)k0 * 1024);
        float4 b1 = *(const float4*)(Bg + (size_t)(k0 + 8) * 1024);
        __syncthreads();
        As[acol + 0][arow] = a0.x; As[acol + 1][arow] = a0.y;
        As[acol + 2][arow] = a0.z; As[acol + 3][arow] = a0.w;
        As[acol + 0][arow + 64] = a1.x; As[acol + 1][arow + 64] = a1.y;
        As[acol + 2][arow + 64] = a1.z; As[acol + 3][arow + 64] = a1.w;
        *(float4*)&Bs[brow][bcol] = b0;
        *(float4*)&Bs[brow + 8][bcol] = b1;
        __syncthreads();
#pragma unroll
        for (int kk = 0; kk < 16; kk++) {
            float4 aA = *(const float4*)&As[kk][tm];
            float4 aB = *(const float4*)&As[kk][tm + 4];
            float4 bA = *(const float4*)&Bs[kk][tn];
            float4 bB = *(const float4*)&Bs[kk][tn + 4];
            uint64_t b2[4] = { packf2(bA.x, bA.y), packf2(bA.z, bA.w),
                               packf2(bB.x, bB.y), packf2(bB.z, bB.w) };
            float av[8] = { aA.x, aA.y, aA.z, aA.w, aB.x, aB.y, aB.z, aB.w };
#pragma unroll
            for (int i = 0; i < 8; i++) {
                uint64_t ad = f2dup(av[i]);
#pragma unroll
                for (int j = 0; j < 4; j++) acc[i][j] = fma2(ad, b2[j], acc[i][j]);
            }
        }
    }

    float* Cg = g_U + (size_t)(m0 + tm) * 1024 + n0 + tn;
#pragma unroll
    for (int i = 0; i < 8; i++)
#pragma unroll
        for (int j = 0; j < 4; j++) {
            float2 f = u2f2(acc[i][j]);
            *(float2*)(Cg + (size_t)i * 1024 + j * 2) = f;
        }
}

// ---------------- Kernel 3: output sweep ----------------
// One CTA per (b, l0). Sweeps U through the 10 output cores, writes per-(b,l)
// partial rows (taking ring bond r == l) into g_S[bl*1024 + p].
__global__ __launch_bounds__(256) void output_sweep_kernel(const float* __restrict__ oc)
{
    extern __shared__ float sm[];
    float* Mc   = sm;                 // 4000, permuted: M_j[(r*2+d)*20 + (p*10+s)] = core_j[r,p,d,s]
    float* bufA = sm + 4000;
    float* bufB = bufA + 10240;
    const int tid = threadIdx.x;
    const int bl = blockIdx.x;
    const int l = bl % 10;
    const size_t rowbase = (size_t)bl * 10;

    for (int t = tid; t < 4000; t += 256) {
        int j = t / 400, rem = t % 400;
        int a = rem / 20, bc = rem % 20;
        int rr = a >> 1, d = a & 1, p = bc / 10, s = bc % 10;
        Mc[t] = oc[j * 400 + rr * 40 + p * 20 + d * 10 + s];
    }
    for (int idx = tid; idx < 10240; idx += 256)
        bufA[idx] = g_U[rowbase * 1024 + idx];   // state (P=1, r=10, D=1024)
    __syncthreads();

    float* cur = bufA;
    float* nxt = bufB;
    for (int j = 0; j < 10; j++) {
        sweep_step(cur, nxt, Mc + j * 400, 512 >> j, 9 - j, tid);
        __syncthreads();
        float* t = cur; cur = nxt; nxt = t;
    }

    // final state: cur[p*10 + r]; keep r == l (ring trace) as this CTA's partial.
    for (int p = tid; p < 1024; p += 256)
        g_S[(size_t)bl * 1024 + p] = cur[p * 10 + l];
}

// ---------------- Kernel 4: reduce partials + bias ----------------
__global__ __launch_bounds__(256) void reduce_kernel(const float* __restrict__ bias,
                                                     float* __restrict__ out)
{
    const int b = blockIdx.x;
    for (int p = threadIdx.x; p < 1024; p += 256) {
        float s = bias[p];
#pragma unroll
        for (int l = 0; l < 10; l++) s += g_S[(size_t)(b * 10 + l) * 1024 + p];
        out[b * 1024 + p] = s;
    }
}

// ---------------- launch ----------------
extern "C" void kernel_launch(void* const* d_in, const int* in_sizes, int n_in,
                              void* d_out, int out_size)
{
    (void)in_sizes; (void)n_in; (void)out_size;
    const float* x    = (const float*)d_in[0];
    const float* ic   = (const float*)d_in[1];
    const float* oc   = (const float*)d_in[2];
    const float* cc   = (const float*)d_in[3];
    const float* bias = (const float*)d_in[4];
    float* out = (float*)d_out;

    const int SMEM_IN  = (1024 + 4000 + 2 * 10240) * 4;  // 102016 B
    const int SMEM_OUT = (4000 + 2 * 10240) * 4;         //  97920 B
    cudaFuncSetAttribute(input_sweep_kernel,  cudaFuncAttributeMaxDynamicSharedMemorySize, SMEM_IN);
    cudaFuncSetAttribute(output_sweep_kernel, cudaFuncAttributeMaxDynamicSharedMemorySize, SMEM_OUT);

    input_sweep_kernel<<<5120, 256, SMEM_IN>>>(x, ic);
    gemm_kernel<<<dim3(8, 400), 256>>>(cc);
    output_sweep_kernel<<<5120, 256, SMEM_OUT>>>(oc);
    reduce_kernel<<<512, 256>>>(bias, out);
}

// round 3
// speedup vs baseline: 1.6965x; 1.6965x over previous
#include <cuda_runtime.h>
#include <cuda_bf16.h>
#include <cstdint>

// Problem constants
//   x: (512,1024) f32; input/output_cores: (10,10,2,2,10) f32
//   central: (1024,1024) f32; bias: (1,1024) f32; out: (512,1024) f32
#define MROWS 51200   // 512 * 10 (l0) * 10 (r)

// Scratch (device globals: allocation-free kernel_launch)
__device__ __nv_bfloat16 g_A [(size_t)MROWS * 2048];  // [Ah | Al] bf16 per row
__device__ __nv_bfloat16 g_Bt[(size_t)1024 * 2048];   // [Bh | Bl], Bt[d][c] = central[c][d]
__device__ float         g_U [(size_t)MROWS * 1024];  // U = S @ central
__device__ float         g_P [(size_t)5120 * 1024];   // per-(b,l) partials

// ========================= helpers =========================
__device__ __forceinline__ uint32_t smem_to_u32(const void* p) {
    uint32_t a;
    asm("{ .reg .u64 t; cvta.to.shared.u64 t, %1; cvt.u32.u64 %0, t; }" : "=r"(a) : "l"(p));
    return a;
}
#define CP_ASYNC16(dst, src) \
    asm volatile("cp.async.cg.shared.global [%0], [%1], 16;" :: "r"(dst), "l"(src) : "memory")
#define CP_COMMIT() asm volatile("cp.async.commit_group;" ::: "memory")
#define CP_WAIT(n)  asm volatile("cp.async.wait_group %0;" :: "n"(n) : "memory")
#define LDMATRIX_X4(r0, r1, r2, r3, addr) \
    asm volatile("ldmatrix.sync.aligned.m8n8.x4.shared.b16 {%0,%1,%2,%3}, [%4];" \
                 : "=r"(r0), "=r"(r1), "=r"(r2), "=r"(r3) : "r"(addr))
#define MMA_BF16(c0, c1, c2, c3, a0, a1, a2, a3, b0, b1) \
    asm volatile("mma.sync.aligned.m16n8k16.row.col.f32.bf16.bf16.f32 " \
                 "{%0,%1,%2,%3}, {%4,%5,%6,%7}, {%8,%9}, {%0,%1,%2,%3};" \
                 : "+f"(c0), "+f"(c1), "+f"(c2), "+f"(c3) \
                 : "r"(a0), "r"(a1), "r"(a2), "r"(a3), "r"(b0), "r"(b1))

// f32x2 helpers
__device__ __forceinline__ uint64_t f2dup(float x) {
    uint64_t r; asm("mov.b64 %0, {%1, %1};" : "=l"(r) : "f"(x)); return r;
}
__device__ __forceinline__ uint64_t fma2(uint64_t a, uint64_t b, uint64_t c) {
    uint64_t d; asm("fma.rn.f32x2 %0, %1, %2, %3;" : "=l"(d) : "l"(a), "l"(b), "l"(c)); return d;
}
__device__ __forceinline__ float2 u2f2(uint64_t u) {
    float2 f; asm("mov.b64 {%0, %1}, %2;" : "=f"(f.x), "=f"(f.y) : "l"(u)); return f;
}

// ========================= shared sweep step =========================
// State: flat[(C_idx*10 + bond)*Q + q], 10240 floats. M is a 20x20 matrix in smem.
__device__ __forceinline__ void sweep_step(const float* __restrict__ cur,
                                           float* __restrict__ nxt,
                                           const float* __restrict__ M,
                                           int Qout, int lq, int tid)
{
    const int Qin = Qout << 1;
    const int j0 = tid, j1 = tid + 256;
    const int q0 = j0 & (Qout - 1), c0 = j0 >> lq;
    const int q1 = j1 & (Qout - 1), c1 = j1 >> lq;

    float v0[20], v1[20];
#pragma unroll
    for (int rr = 0; rr < 10; rr++) {
        int base0 = (c0 * 10 + rr) * Qin + q0;
        v0[2 * rr]     = cur[base0];
        v0[2 * rr + 1] = cur[base0 + Qout];
        int base1 = (c1 * 10 + rr) * Qin + q1;
        v1[2 * rr]     = cur[base1];
        v1[2 * rr + 1] = cur[base1 + Qout];
    }

    uint64_t acc0[10], acc1[10];
#pragma unroll
    for (int t = 0; t < 10; t++) { acc0[t] = 0ull; acc1[t] = 0ull; }

#pragma unroll
    for (int a = 0; a < 20; a++) {
        uint64_t va0 = f2dup(v0[a]);
        uint64_t va1 = f2dup(v1[a]);
        const uint64_t* M2 = (const uint64_t*)(M + a * 20);
#pragma unroll
        for (int b2 = 0; b2 < 10; b2++) {
            uint64_t m2 = M2[b2];
            acc0[b2] = fma2(va0, m2, acc0[b2]);
            acc1[b2] = fma2(va1, m2, acc1[b2]);
        }
    }

#pragma unroll
    for (int b2 = 0; b2 < 10; b2++) {
        float2 f0 = u2f2(acc0[b2]);
        float2 f1 = u2f2(acc1[b2]);
        const int bbA = 2 * b2, bbB = 2 * b2 + 1;
        const int dA = bbA / 10, sA = bbA % 10;
        const int dB = bbB / 10, sB = bbB % 10;
        nxt[((c0 * 2 + dA) * 10 + sA) * Qout + q0] = f0.x;
        nxt[((c0 * 2 + dB) * 10 + sB) * Qout + q0] = f0.y;
        nxt[((c1 * 2 + dA) * 10 + sA) * Qout + q1] = f1.x;
        nxt[((c1 * 2 + dB) * 10 + sB) * Qout + q1] = f1.y;
    }
}

// ========================= Kernel 1: input sweep =========================
__global__ __launch_bounds__(256) void input_sweep_kernel(const float* __restrict__ x,
                                                          const float* __restrict__ ic)
{
    extern __shared__ float sm[];
    float* xs   = sm;
    float* Mc   = sm + 1024;
    float* bufA = sm + 1024 + 4000;
    float* bufB = bufA + 10240;
    const int tid = threadIdx.x;
    const int bl = blockIdx.x;
    const int b = bl / 10, l = bl % 10;

    for (int t = tid; t < 1024; t += 256) xs[t] = x[b * 1024 + t];
    for (int t = tid; t < 4000; t += 256) Mc[t] = ic[t];
    __syncthreads();

    for (int idx = tid; idx < 10240; idx += 256) {
        int q  = idx & 511;
        int cs = idx >> 9;
        int c = cs / 10, s = cs % 10;
        float w0 = Mc[((l * 2 + 0) * 2 + c) * 10 + s];
        float w1 = Mc[((l * 2 + 1) * 2 + c) * 10 + s];
        bufA[idx] = xs[q] * w0 + xs[512 + q] * w1;
    }

    float* cur = bufA;
    float* nxt = bufB;
    for (int i = 1; i < 10; i++) {
        __syncthreads();
        sweep_step(cur, nxt, Mc + i * 400, 512 >> i, 9 - i, tid);
        float* t = cur; cur = nxt; nxt = t;
    }
    __syncthreads();

    // final: cur[c*10 + r] -> bf16 hi/lo rows of g_A
    const size_t rowbase = (size_t)bl * 10;
    for (int idx = tid; idx < 5120; idx += 256) {
        int rr = idx / 512, cp2 = idx % 512;
        int c0 = cp2 * 2;
        float va = cur[c0 * 10 + rr];
        float vb = cur[(c0 + 1) * 10 + rr];
        __nv_bfloat16 ha = __float2bfloat16(va);
        __nv_bfloat16 hb = __float2bfloat16(vb);
        __nv_bfloat16 la = __float2bfloat16(va - __bfloat162float(ha));
        __nv_bfloat16 lb = __float2bfloat16(vb - __bfloat162float(hb));
        size_t row = rowbase + rr;
        __nv_bfloat162 hi; hi.x = ha; hi.y = hb;
        __nv_bfloat162 lo; lo.x = la; lo.y = lb;
        *(__nv_bfloat162*)&g_A[row * 2048 + c0]        = hi;
        *(__nv_bfloat162*)&g_A[row * 2048 + 1024 + c0] = lo;
    }
}

// ========================= Kernel 2: B transpose+split =========================
__global__ __launch_bounds__(256) void bconv_kernel(const float* __restrict__ cc)
{
    __shared__ float t[32][33];
    const int tx = threadIdx.x, ty = threadIdx.y;   // (32, 8)
    const int c0 = blockIdx.x * 32, d0 = blockIdx.y * 32;
#pragma unroll
    for (int i = 0; i < 32; i += 8)
        t[ty + i][tx] = cc[(size_t)(c0 + ty + i) * 1024 + d0 + tx];
    __syncthreads();
#pragma unroll
    for (int i = 0; i < 32; i += 8) {
        int d = ty + i;
        float v = t[tx][d];   // central[c0+tx][d0+d]
        __nv_bfloat16 h = __float2bfloat16(v);
        __nv_bfloat16 lo = __float2bfloat16(v - __bfloat162float(h));
        g_Bt[(size_t)(d0 + d) * 2048 + c0 + tx]        = h;
        g_Bt[(size_t)(d0 + d) * 2048 + 1024 + c0 + tx] = lo;
    }
}

// ========================= Kernel 3: HMMA GEMM =========================
// U(51200x1024) = A_split @ Bt_split^T, 3-term bf16 (virtual K = 3072).
// CTA tile 128x256, K-chunks of 64; 16 warps (4x4), warp tile 32x64.
#define G_STAGES 4
#define G_ABYTES 16384            // 128 rows x 128B
#define G_BBYTES 32768            // 256 rows x 128B
#define G_STAGE_BYTES (G_ABYTES + G_BBYTES)
#define G_NCHUNKS 48

__device__ __forceinline__ void gemm_load_chunk(int kc, int stage, int m0, int n0,
                                                uint32_t smem_base, int tid)
{
    const int block = kc >> 4, j = kc & 15;
    const int acol = ((block == 1) ? 1024 : 0) + j * 64;
    const int bcol = ((block == 2) ? 1024 : 0) + j * 64;
    const uint32_t abase = smem_base + stage * G_STAGE_BYTES;
    const uint32_t bbase = abase + G_ABYTES;
#pragma unroll
    for (int i = 0; i < 2; i++) {                 // A: 1024 x 16B
        int idx = tid + i * 512;
        int r = idx >> 3, c = idx & 7;
        uint32_t dst = abase + (uint32_t)(r * 128 + ((c ^ (r & 7)) << 4));
        const void* src = (const void*)(g_A + (size_t)(m0 + r) * 2048 + acol + c * 8);
        CP_ASYNC16(dst, src);
    }
#pragma unroll
    for (int i = 0; i < 4; i++) {                 // B: 2048 x 16B
        int idx = tid + i * 512;
        int r = idx >> 3, c = idx & 7;
        uint32_t dst = bbase + (uint32_t)(r * 128 + ((c ^ (r & 7)) << 4));
        const void* src = (const void*)(g_Bt + (size_t)(n0 + r) * 2048 + bcol + c * 8);
        CP_ASYNC16(dst, src);
    }
}

__global__ __launch_bounds__(512, 1) void gemm_mma_kernel()
{
    extern __shared__ char smc[];
    const uint32_t smem_base = smem_to_u32(smc);
    const int tid  = threadIdx.x;
    const int wid  = tid >> 5;
    const int lane = tid & 31;
    const int m0 = blockIdx.y * 128;
    const int n0 = blockIdx.x * 256;
    const int wm = (wid & 3) * 32;      // warp row in tile
    const int wn = (wid >> 2) * 64;     // warp col in tile

    float acc[2][8][4];
#pragma unroll
    for (int i = 0; i < 2; i++)
#pragma unroll
        for (int j = 0; j < 8; j++)
#pragma unroll
            for (int k = 0; k < 4; k++) acc[i][j][k] = 0.f;

    // prologue
#pragma unroll
    for (int c = 0; c < 3; c++) { gemm_load_chunk(c, c, m0, n0, smem_base, tid); CP_COMMIT(); }

    // per-lane ldmatrix address components
    const int matA = lane >> 3;
    const int rowA_lo = (lane & 7) + ((matA & 1) << 3);    // row within m16 tile
    const int kselA = matA >> 1;                            // 0: k-lo, 1: k-hi
    const int matB = lane >> 3;
    const int rowB_lo = (lane & 7) + ((matB >> 1) << 3);   // row within n16 pair
    const int kselB = matB & 1;

    for (int kc = 0; kc < G_NCHUNKS; kc++) {
        CP_WAIT(2);
        __syncthreads();
        int pre = kc + 3; if (pre > G_NCHUNKS - 1) pre = G_NCHUNKS - 1;
        gemm_load_chunk(pre, (kc + 3) & 3, m0, n0, smem_base, tid);
        CP_COMMIT();

        const uint32_t abase = smem_base + (kc & 3) * G_STAGE_BYTES;
        const uint32_t bbase = abase + G_ABYTES;

#pragma unroll
        for (int kk = 0; kk < 4; kk++) {
            uint32_t af[2][4];
#pragma unroll
            for (int mt = 0; mt < 2; mt++) {
                int r = wm + mt * 16 + rowA_lo;
                int ch = 2 * kk + kselA;
                uint32_t addr = abase + (uint32_t)(r * 128 + ((ch ^ (r & 7)) << 4));
                LDMATRIX_X4(af[mt][0], af[mt][1], af[mt][2], af[mt][3], addr);
            }
            uint32_t bf[4][4];
#pragma unroll
            for (int p = 0; p < 4; p++) {
                int r = wn + p * 16 + rowB_lo;
                int ch = 2 * kk + kselB;
                uint32_t addr = bbase + (uint32_t)(r * 128 + ((ch ^ (r & 7)) << 4));
                LDMATRIX_X4(bf[p][0], bf[p][1], bf[p][2], bf[p][3], addr);
            }
#pragma unroll
            for (int mt = 0; mt < 2; mt++)
#pragma unroll
                for (int nt = 0; nt < 8; nt++) {
                    int p = nt >> 1, hi = nt & 1;
                    MMA_BF16(acc[mt][nt][0], acc[mt][nt][1], acc[mt][nt][2], acc[mt][nt][3],
                             af[mt][0], af[mt][1], af[mt][2], af[mt][3],
                             bf[p][2 * hi], bf[p][2 * hi + 1]);
                }
        }
    }

    // epilogue: write accum to g_U
#pragma unroll
    for (int mt = 0; mt < 2; mt++) {
        int row = m0 + wm + mt * 16 + (lane >> 2);
#pragma unroll
        for (int nt = 0; nt < 8; nt++) {
            int col = n0 + wn + nt * 8 + (lane & 3) * 2;
            *(float2*)&g_U[(size_t)row * 1024 + col]       = make_float2(acc[mt][nt][0], acc[mt][nt][1]);
            *(float2*)&g_U[(size_t)(row + 8) * 1024 + col] = make_float2(acc[mt][nt][2], acc[mt][nt][3]);
        }
    }
}

// ========================= Kernel 4: output sweep =========================
__global__ __launch_bounds__(256) void output_sweep_kernel(const float* __restrict__ oc)
{
    extern __shared__ float sm[];
    float* Mc   = sm;
    float* bufA = sm + 4000;
    float* bufB = bufA + 10240;
    const int tid = threadIdx.x;
    const int bl = blockIdx.x;
    const int l = bl % 10;
    const size_t rowbase = (size_t)bl * 10;

    for (int t = tid; t < 4000; t += 256) {
        int j = t / 400, rem = t % 400;
        int a = rem / 20, bc = rem % 20;
        int rr = a >> 1, d = a & 1, p = bc / 10, s = bc % 10;
        Mc[t] = oc[j * 400 + rr * 40 + p * 20 + d * 10 + s];
    }
    for (int idx = tid; idx < 10240; idx += 256)
        bufA[idx] = g_U[rowbase * 1024 + idx];
    __syncthreads();

    float* cur = bufA;
    float* nxt = bufB;
    for (int j = 0; j < 10; j++) {
        sweep_step(cur, nxt, Mc + j * 400, 512 >> j, 9 - j, tid);
        __syncthreads();
        float* t = cur; cur = nxt; nxt = t;
    }

    for (int p = tid; p < 1024; p += 256)
        g_P[(size_t)bl * 1024 + p] = cur[p * 10 + l];
}

// ========================= Kernel 5: reduce =========================
__global__ __launch_bounds__(256) void reduce_kernel(const float* __restrict__ bias,
                                                     float* __restrict__ out)
{
    const int b = blockIdx.x;
    for (int p = threadIdx.x; p < 1024; p += 256) {
        float s = bias[p];
#pragma unroll
        for (int l = 0; l < 10; l++) s += g_P[(size_t)(b * 10 + l) * 1024 + p];
        out[b * 1024 + p] = s;
    }
}

// ========================= launch =========================
extern "C" void kernel_launch(void* const* d_in, const int* in_sizes, int n_in,
                              void* d_out, int out_size)
{
    (void)in_sizes; (void)n_in; (void)out_size;
    const float* x    = (const float*)d_in[0];
    const float* ic   = (const float*)d_in[1];
    const float* oc   = (const float*)d_in[2];
    const float* cc   = (const float*)d_in[3];
    const float* bias = (const float*)d_in[4];
    float* out = (float*)d_out;

    const int SMEM_IN   = (1024 + 4000 + 2 * 10240) * 4;    // 102016 B
    const int SMEM_OUT  = (4000 + 2 * 10240) * 4;           //  97920 B
    const int SMEM_GEMM = G_STAGES * G_STAGE_BYTES;         // 196608 B
    cudaFuncSetAttribute(input_sweep_kernel,  cudaFuncAttributeMaxDynamicSharedMemorySize, SMEM_IN);
    cudaFuncSetAttribute(output_sweep_kernel, cudaFuncAttributeMaxDynamicSharedMemorySize, SMEM_OUT);
    cudaFuncSetAttribute(gemm_mma_kernel,     cudaFuncAttributeMaxDynamicSharedMemorySize, SMEM_GEMM);

    input_sweep_kernel<<<5120, 256, SMEM_IN>>>(x, ic);
    bconv_kernel<<<dim3(32, 32), dim3(32, 8)>>>(cc);
    gemm_mma_kernel<<<dim3(4, 400), 512, SMEM_GEMM>>>();
    output_sweep_kernel<<<5120, 256, SMEM_OUT>>>(oc);
    reduce_kernel<<<512, 256>>>(bias, out);
}